// round 9
// baseline (speedup 1.0000x reference)
#include <cuda_runtime.h>
#include <math.h>

#define BB 8
#define CH 16
#define NFREQ (24*24*12)   // 6912

// Scratch
__device__ float2 g_bufA[BB*CH*64*64*12];   // [bc][ix][iy][kt] (fwd only)
__device__ float2 g_bufB[BB*CH*64*24*12];   // [bc][ix][kyi][kt] fwd / [bo][ix][kyi][kt] inv
__device__ float2 g_XFP[4][NFREQ*128];      // x-chunk partials [cx][f][bc]
__device__ float2 g_OF2[NFREQ*128];         // [f][bc]
__device__ float2 g_WT[NFREQ*256];          // [f][i*16+o]

// ---------------------------------------------------------------------------
// KW: weight transpose into frequency-major layout, tiled through smem so both
// global reads and writes are coalesced. Block = (kxi,kyi), 256 threads.
// ---------------------------------------------------------------------------
__global__ void kw_prep(const float* __restrict__ w1, const float* __restrict__ w2,
                        const float* __restrict__ w3, const float* __restrict__ w4) {
    __shared__ float2 sW[12][258];
    int bidx = blockIdx.x;                  // kxi*24 + kyi
    int kxi = bidx / 24, kyi = bidx % 24;
    const float* w = (kxi < 12) ? ((kyi < 12) ? w1 : w3)
                                : ((kyi < 12) ? w2 : w4);
    int kxp = kxi % 12, kyp = kyi % 12;
    int tid = threadIdx.x;                  // 256
    long base = ((long)kxp * 12 + kyp) * 12;
    for (int e = tid; e < 3072; e += 256) {
        int r = e / 12, kt = e % 12;        // read 12 contiguous float2 per r
        sW[kt][r] = ((const float2*)w)[(long)r * 1728 + base + kt];
    }
    __syncthreads();
    long f0 = (long)kxi * 288 + kyi * 12;
    for (int e = tid; e < 3072; e += 256) {
        int kt = e / 256, r = e % 256;      // write 256 contiguous float2 per kt
        g_WT[(f0 + kt) * 256 + r] = sW[kt][r];
    }
}

// ---------------------------------------------------------------------------
// K1: real t-DFT 64 -> 12 modes, +32 parity pairing. 1 thread = 1 row.
// ---------------------------------------------------------------------------
__global__ void k1_fft_t(const float* __restrict__ x) {
    __shared__ float  xs[128][65];
    __shared__ __align__(16) float2 twm[32][12];
    int tid = threadIdx.x;  // 128
    for (int e = tid; e < 384; e += 128) {
        int tp = e / 12, k = e % 12;
        float sn, cs; sincospif((float)((tp * k) & 63) / 32.0f, &sn, &cs);
        twm[tp][k] = make_float2(cs, sn);
    }
    long base = (long)blockIdx.x * 128 * 64;
    const float4* xv = (const float4*)(x + base);
    for (int e = tid; e < 2048; e += 128) {
        float4 v = xv[e];
        int row = e >> 4, col = (e & 15) << 2;
        xs[row][col] = v.x; xs[row][col+1] = v.y; xs[row][col+2] = v.z; xs[row][col+3] = v.w;
    }
    __syncthreads();

    float re[12], im[12];
    #pragma unroll
    for (int k = 0; k < 12; k++) { re[k] = 0.f; im[k] = 0.f; }

    #pragma unroll 4
    for (int tp = 0; tp < 32; tp++) {
        float a = xs[tid][tp], b = xs[tid][tp + 32];
        float ve = a + b, vo = a - b;
        const float4* tp4 = (const float4*)&twm[tp][0];
        #pragma unroll
        for (int j = 0; j < 6; j++) {
            float4 w = tp4[j];
            re[2*j]   = fmaf(ve, w.x, re[2*j]);
            im[2*j]   = fmaf(-ve, w.y, im[2*j]);
            re[2*j+1] = fmaf(vo, w.z, re[2*j+1]);
            im[2*j+1] = fmaf(-vo, w.w, im[2*j+1]);
        }
    }
    float4* ob = (float4*)&g_bufA[((long)blockIdx.x * 128 + tid) * 12];
    #pragma unroll
    for (int j = 0; j < 6; j++)
        ob[j] = make_float4(re[2*j], im[2*j], re[2*j+1], im[2*j+1]);
}

// ---------------------------------------------------------------------------
// K2: complex y-DFT 64 -> 24 modes, +32 parity pairing. Conflict-free padded
// smem (per-ixl stride 389 float2). Block=(bc, 8 ix), 96 thr.
// ---------------------------------------------------------------------------
__global__ void k2_fft_y() {
    __shared__ float2 sIn[8 * 389 + 3];    // [ixl]*389 + [h]*192 + yy*12 + kt
    __shared__ __align__(16) float2 twy[32][24];
    int tid = threadIdx.x;  // 96
    for (int e = tid; e < 768; e += 96) {
        int yp = e / 24, kyi = e % 24;
        int ky = (kyi < 12) ? kyi : kyi + 40;
        float sn, cs; sincospif((float)((ky * yp) & 63) / 32.0f, &sn, &cs);
        twy[yp][kyi] = make_float2(cs, sn);
    }
    int bc  = blockIdx.x >> 3;
    int ixg = (blockIdx.x & 7) * 8;
    int ixl = tid / 12, kt = tid % 12;

    float ar[24], ai[24];
    #pragma unroll
    for (int i = 0; i < 24; i++) { ar[i] = 0.f; ai[i] = 0.f; }

    for (int cy = 0; cy < 2; cy++) {
        __syncthreads();
        for (int e = tid; e < 3072; e += 96) {
            int il = e / 384, rem = e % 384, h = rem / 192, r2 = rem % 192;
            sIn[il * 389 + h * 192 + r2] =
                g_bufA[((long)(bc*64 + ixg + il) * 64 + cy*16 + h*32) * 12 + r2];
        }
        __syncthreads();
        const float2* sRow = &sIn[ixl * 389 + kt];
        for (int yy = 0; yy < 16; yy++) {
            int yp = cy * 16 + yy;
            float2 v1 = sRow[yy * 12];
            float2 v2 = sRow[192 + yy * 12];
            float vex = v1.x + v2.x, vey = v1.y + v2.y;
            float vox = v1.x - v2.x, voy = v1.y - v2.y;
            const float4* tp4 = (const float4*)&twy[yp][0];
            #pragma unroll
            for (int j = 0; j < 12; j++) {
                float4 w = tp4[j];
                ar[2*j]   = fmaf(vex, w.x, fmaf( vey, w.y, ar[2*j]));
                ai[2*j]   = fmaf(vey, w.x, fmaf(-vex, w.y, ai[2*j]));
                ar[2*j+1] = fmaf(vox, w.z, fmaf( voy, w.w, ar[2*j+1]));
                ai[2*j+1] = fmaf(voy, w.z, fmaf(-vox, w.w, ai[2*j+1]));
            }
        }
    }
    long obase = ((long)(bc * 64 + ixg + ixl) * 24) * 12 + kt;
    #pragma unroll
    for (int kyi = 0; kyi < 24; kyi++)
        g_bufB[obase + kyi * 12] = make_float2(ar[kyi], ai[kyi]);
}

// ---------------------------------------------------------------------------
// K3: complex x-DFT 64 -> 24 modes, +32 parity pairing, split 4-way over x.
// Block = (bc, cx), 288 thr = (kyi*12+kt). Writes partials g_XFP[cx][f][bc].
// ---------------------------------------------------------------------------
__global__ void k3_fft_x() {
    __shared__ __align__(16) float2 sIn[8][2][288];
    __shared__ __align__(16) float2 twx[32][24];
    int tid = threadIdx.x;  // 288
    for (int e = tid; e < 768; e += 288) {
        int xp = e / 24, kxi = e % 24;
        int kx = (kxi < 12) ? kxi : kxi + 40;
        float sn, cs; sincospif((float)((kx * xp) & 63) / 32.0f, &sn, &cs);
        twx[xp][kxi] = make_float2(cs, sn);
    }
    int bc = blockIdx.x >> 2, cx = blockIdx.x & 3;

    float ar[24], ai[24];
    #pragma unroll
    for (int i = 0; i < 24; i++) { ar[i] = 0.f; ai[i] = 0.f; }

    for (int e = tid; e < 2304; e += 288) {
        int xl = e / 288, h = (e / 144) & 1, r = e % 144;
        const float4* src = (const float4*)&g_bufB[((long)(bc * 64 + cx*8 + xl + h*32)) * 288];
        ((float4*)&sIn[xl][h][0])[r] = src[r];
    }
    __syncthreads();
    #pragma unroll 2
    for (int xl = 0; xl < 8; xl++) {
        int xp = cx * 8 + xl;
        float2 v1 = sIn[xl][0][tid];
        float2 v2 = sIn[xl][1][tid];
        float vex = v1.x + v2.x, vey = v1.y + v2.y;
        float vox = v1.x - v2.x, voy = v1.y - v2.y;
        const float4* tp4 = (const float4*)&twx[xp][0];
        #pragma unroll
        for (int j = 0; j < 12; j++) {
            float4 w = tp4[j];
            ar[2*j]   = fmaf(vex, w.x, fmaf( vey, w.y, ar[2*j]));
            ai[2*j]   = fmaf(vey, w.x, fmaf(-vex, w.y, ai[2*j]));
            ar[2*j+1] = fmaf(vox, w.z, fmaf( voy, w.w, ar[2*j+1]));
            ai[2*j+1] = fmaf(voy, w.z, fmaf(-vox, w.w, ai[2*j+1]));
        }
    }
    #pragma unroll
    for (int kxi = 0; kxi < 24; kxi++)
        g_XFP[cx][(long)(kxi * 288 + tid) * 128 + bc] = make_float2(ar[kxi], ai[kxi]);
}

// ---------------------------------------------------------------------------
// K4: per-frequency 16x16 complex mix; sums the 4 x-chunk partials.
// 4 freqs/block, 512 threads.
// ---------------------------------------------------------------------------
__global__ void k4_mix() {
    __shared__ __align__(16) float2 ws[4][256];
    __shared__ float2 xs[4][128];
    int tid  = threadIdx.x;            // 512
    int slot = tid >> 7, st = tid & 127;
    int f = blockIdx.x * 4 + slot;
    {
        const float4* wp = (const float4*)&g_WT[(long)f * 256];
        ((float4*)&ws[slot][0])[st] = wp[st];
    }
    {
        long idx = (long)f * 128 + st;
        float2 a = g_XFP[0][idx], b = g_XFP[1][idx];
        float2 c = g_XFP[2][idx], d = g_XFP[3][idx];
        xs[slot][st] = make_float2(a.x + b.x + c.x + d.x, a.y + b.y + c.y + d.y);
    }
    __syncthreads();
    int b = st >> 4, o = st & 15;
    float re = 0.f, im = 0.f;
    #pragma unroll
    for (int i = 0; i < 16; i++) {
        float2 a  = xs[slot][b * 16 + i];
        float2 wv = ws[slot][i * 16 + o];
        re = fmaf(a.x, wv.x, fmaf(-a.y, wv.y, re));
        im = fmaf(a.x, wv.y, fmaf( a.y, wv.x, im));
    }
    g_OF2[(long)f * 128 + st] = make_float2(re, im);
}

// ---------------------------------------------------------------------------
// K5: inverse x-DFT 24 -> 64 with conjugate-mode pairing (S/D in smem).
// Block = (bo, 4 kyi), 256 thr = (kslot, ix).
// ---------------------------------------------------------------------------
__global__ void k5_ifft_x() {
    __shared__ __align__(16) float4 sSD[4][11][12];
    __shared__ __align__(16) float2 sV0[4][12];
    __shared__ __align__(16) float2 sV12[4][12];
    __shared__ float2 tw[64];
    int tid = threadIdx.x;  // 256
    if (tid < 64) {
        float sn, cs; sincospif((float)tid / 32.0f, &sn, &cs);
        tw[tid] = make_float2(cs, sn);
    }
    int bo  = blockIdx.x / 6;
    int kyg = (blockIdx.x % 6) * 4;
    if (tid < 48) {
        int ks = tid / 12, kt = tid % 12;
        sV0[ks][kt]  = g_OF2[(long)(0 * 288 + (kyg + ks) * 12 + kt) * 128 + bo];
        sV12[ks][kt] = g_OF2[(long)(12 * 288 + (kyg + ks) * 12 + kt) * 128 + bo];
    }
    for (int e = tid; e < 528; e += 256) {
        int ks = e / 132, r = e % 132, kp = r / 12 + 1, kt = r % 12;
        float2 v1 = g_OF2[(long)(kp * 288 + (kyg + ks) * 12 + kt) * 128 + bo];
        float2 v2 = g_OF2[(long)((24 - kp) * 288 + (kyg + ks) * 12 + kt) * 128 + bo];
        sSD[ks][kp - 1][kt] = make_float4(v1.x + v2.x, v1.y + v2.y, v1.x - v2.x, v1.y - v2.y);
    }
    __syncthreads();
    int kslot = tid >> 6, ix = tid & 63;

    float ar[12], ai[12];
    {
        const float4* v0 = (const float4*)&sV0[kslot][0];
        #pragma unroll
        for (int j = 0; j < 6; j++) {
            float4 v = v0[j];
            ar[2*j] = v.x; ai[2*j] = v.y; ar[2*j+1] = v.z; ai[2*j+1] = v.w;
        }
    }
    #pragma unroll
    for (int kp = 1; kp < 12; kp++) {
        float2 w = tw[(kp * ix) & 63];
        #pragma unroll
        for (int kt = 0; kt < 12; kt++) {
            float4 sd = sSD[kslot][kp - 1][kt];
            ar[kt] = fmaf(sd.x, w.x, fmaf(-sd.w, w.y, ar[kt]));
            ai[kt] = fmaf(sd.z, w.y, fmaf( sd.y, w.x, ai[kt]));
        }
    }
    {
        float2 w = tw[(52 * ix) & 63];
        const float4* vp = (const float4*)&sV12[kslot][0];
        #pragma unroll
        for (int j = 0; j < 6; j++) {
            float4 v = vp[j];
            ar[2*j]   = fmaf(v.x, w.x, fmaf(-v.y, w.y, ar[2*j]));
            ai[2*j]   = fmaf(v.x, w.y, fmaf( v.y, w.x, ai[2*j]));
            ar[2*j+1] = fmaf(v.z, w.x, fmaf(-v.w, w.y, ar[2*j+1]));
            ai[2*j+1] = fmaf(v.z, w.y, fmaf( v.w, w.x, ai[2*j+1]));
        }
    }
    float4* ob = (float4*)&g_bufB[((long)(bo * 64 + ix) * 24 + kyg + kslot) * 12];
    #pragma unroll
    for (int j = 0; j < 6; j++)
        ob[j] = make_float4(ar[2*j], ai[2*j], ar[2*j+1], ai[2*j+1]);
}

// ---------------------------------------------------------------------------
// F3: fused inverse y-DFT (conj-paired S/D) + inverse real t-DFT (t/t+32
// parity) + ReLU + 16x16 channel mix + bias. Block = (b,ix), 256 threads,
// 8 iy per chunk, dynamic smem (~51KB). All float4-cast regions 16B-aligned.
// ---------------------------------------------------------------------------
__global__ void f3_inv(const float* __restrict__ lo_w, const float* __restrict__ lo_b,
                       float* __restrict__ out) {
    extern __shared__ __align__(16) float sm[];
    float4* sSD  = (float4*)sm;                    // [16][11][12]  floats [0,8448)
    float2* H    = (float2*)(sm + 8448);           // [16][8][12]   floats [8448,11520)
    float2* sV0  = (float2*)(sm + 11520);          // [16][12]
    float2* sV12 = (float2*)(sm + 11904);          // [16][12]
    float2* tw   = (float2*)(sm + 12288);          // [64]
    float*  lwT  = sm + 12416;                     // [16][16] c-major
    float*  lb   = sm + 12672;                     // [16]

    int tid = threadIdx.x;  // 256
    if (tid < 64) {
        float sn, cs; sincospif((float)tid / 32.0f, &sn, &cs);
        tw[tid] = make_float2(cs, sn);
    }
    lwT[(tid & 15) * 16 + (tid >> 4)] = lo_w[tid];
    if (tid < 16) lb[tid] = lo_b[tid];

    int b = blockIdx.x >> 6, ixx = blockIdx.x & 63;
    for (int e = tid; e < 192; e += 256) {
        int o = e / 12, kt = e % 12;
        long rbase = ((long)((b*16+o) * 64 + ixx) * 24) * 12;
        sV0[e]  = g_bufB[rbase + kt];
        sV12[e] = g_bufB[rbase + 144 + kt];
    }
    for (int e = tid; e < 2112; e += 256) {
        int o = e / 132, r = e % 132, kp = r / 12 + 1, kt = r % 12;
        long rbase = ((long)((b*16+o) * 64 + ixx) * 24) * 12;
        float2 v1 = g_bufB[rbase + kp * 12 + kt];
        float2 v2 = g_bufB[rbase + (24 - kp) * 12 + kt];
        sSD[e] = make_float4(v1.x + v2.x, v1.y + v2.y, v1.x - v2.x, v1.y - v2.y);
    }
    __syncthreads();

    int iyl = tid >> 5, tp = tid & 31;
    float c2[12], s2[12];
    #pragma unroll
    for (int k = 1; k < 12; k++) {
        float2 w = tw[(k * tp) & 63];
        c2[k] = 2.0f * w.x;
        s2[k] = 2.0f * w.y;
    }
    const float scale = 1.0f / (64.0f * 64.0f * 64.0f);

    for (int cy = 0; cy < 8; cy++) {
        // phase A: inverse y for 8 iy
        #pragma unroll
        for (int j = 0; j < 6; j++) {
            int e = tid + j * 256;
            int o = e / 96, rem = e % 96;
            int iyA = cy * 8 + rem / 12, kt = rem % 12;
            float2 v0 = sV0[o * 12 + kt];
            float arx = v0.x, aix = v0.y;
            #pragma unroll
            for (int kp = 1; kp < 12; kp++) {
                float2 w = tw[(kp * iyA) & 63];
                float4 sd = sSD[o * 132 + (kp - 1) * 12 + kt];
                arx = fmaf(sd.x, w.x, fmaf(-sd.w, w.y, arx));
                aix = fmaf(sd.z, w.y, fmaf( sd.y, w.x, aix));
            }
            float2 w = tw[(52 * iyA) & 63];
            float2 v12 = sV12[o * 12 + kt];
            arx = fmaf(v12.x, w.x, fmaf(-v12.y, w.y, arx));
            aix = fmaf(v12.x, w.y, fmaf( v12.y, w.x, aix));
            H[(o * 8 + rem / 12) * 12 + kt] = make_float2(arx, aix);
        }
        __syncthreads();

        // phase B: t-inverse parity + relu + mix
        float acc1[16], acc2[16];
        #pragma unroll
        for (int o = 0; o < 16; o++) { acc1[o] = lb[o]; acc2[o] = lb[o]; }

        #pragma unroll 4
        for (int c = 0; c < 16; c++) {
            const float4* Fp = (const float4*)&H[(c * 8 + iyl) * 12];
            float4 a0 = Fp[0], a1 = Fp[1], a2 = Fp[2], a3 = Fp[3], a4 = Fp[4], a5 = Fp[5];
            float po = fmaf(a0.z, c2[1],  -a0.w * s2[1]);
            float pe = fmaf(a1.x, c2[2],  -a1.y * s2[2]);
            po = fmaf(a1.z, c2[3],  fmaf(-a1.w, s2[3],  po));
            pe = fmaf(a2.x, c2[4],  fmaf(-a2.y, s2[4],  pe));
            po = fmaf(a2.z, c2[5],  fmaf(-a2.w, s2[5],  po));
            pe = fmaf(a3.x, c2[6],  fmaf(-a3.y, s2[6],  pe));
            po = fmaf(a3.z, c2[7],  fmaf(-a3.w, s2[7],  po));
            pe = fmaf(a4.x, c2[8],  fmaf(-a4.y, s2[8],  pe));
            po = fmaf(a4.z, c2[9],  fmaf(-a4.w, s2[9],  po));
            pe = fmaf(a5.x, c2[10], fmaf(-a5.y, s2[10], pe));
            po = fmaf(a5.z, c2[11], fmaf(-a5.w, s2[11], po));
            float base = a0.x + pe;
            float v1 = fmaxf((base + po) * scale, 0.0f);   // t = tp
            float v2 = fmaxf((base - po) * scale, 0.0f);   // t = tp+32
            const float4* lp = (const float4*)&lwT[c * 16];
            float4 l0 = lp[0], l1 = lp[1], l2 = lp[2], l3 = lp[3];
            acc1[0]  = fmaf(l0.x, v1, acc1[0]);  acc2[0]  = fmaf(l0.x, v2, acc2[0]);
            acc1[1]  = fmaf(l0.y, v1, acc1[1]);  acc2[1]  = fmaf(l0.y, v2, acc2[1]);
            acc1[2]  = fmaf(l0.z, v1, acc1[2]);  acc2[2]  = fmaf(l0.z, v2, acc2[2]);
            acc1[3]  = fmaf(l0.w, v1, acc1[3]);  acc2[3]  = fmaf(l0.w, v2, acc2[3]);
            acc1[4]  = fmaf(l1.x, v1, acc1[4]);  acc2[4]  = fmaf(l1.x, v2, acc2[4]);
            acc1[5]  = fmaf(l1.y, v1, acc1[5]);  acc2[5]  = fmaf(l1.y, v2, acc2[5]);
            acc1[6]  = fmaf(l1.z, v1, acc1[6]);  acc2[6]  = fmaf(l1.z, v2, acc2[6]);
            acc1[7]  = fmaf(l1.w, v1, acc1[7]);  acc2[7]  = fmaf(l1.w, v2, acc2[7]);
            acc1[8]  = fmaf(l2.x, v1, acc1[8]);  acc2[8]  = fmaf(l2.x, v2, acc2[8]);
            acc1[9]  = fmaf(l2.y, v1, acc1[9]);  acc2[9]  = fmaf(l2.y, v2, acc2[9]);
            acc1[10] = fmaf(l2.z, v1, acc1[10]); acc2[10] = fmaf(l2.z, v2, acc2[10]);
            acc1[11] = fmaf(l2.w, v1, acc1[11]); acc2[11] = fmaf(l2.w, v2, acc2[11]);
            acc1[12] = fmaf(l3.x, v1, acc1[12]); acc2[12] = fmaf(l3.x, v2, acc2[12]);
            acc1[13] = fmaf(l3.y, v1, acc1[13]); acc2[13] = fmaf(l3.y, v2, acc2[13]);
            acc1[14] = fmaf(l3.z, v1, acc1[14]); acc2[14] = fmaf(l3.z, v2, acc2[14]);
            acc1[15] = fmaf(l3.w, v1, acc1[15]); acc2[15] = fmaf(l3.w, v2, acc2[15]);
        }

        int iy = cy * 8 + iyl;
        long obase = (long)b * 16 * 262144 + ((long)ixx * 64 + iy) * 64;
        #pragma unroll
        for (int o = 0; o < 16; o++) {
            out[obase + (long)o * 262144 + tp]      = acc1[o];
            out[obase + (long)o * 262144 + tp + 32] = acc2[o];
        }
        __syncthreads();
    }
}

// ---------------------------------------------------------------------------
extern "C" void kernel_launch(void* const* d_in, const int* in_sizes, int n_in,
                              void* d_out, int out_size) {
    const float* x    = (const float*)d_in[0];
    const float* w1   = (const float*)d_in[1];
    const float* w2   = (const float*)d_in[2];
    const float* w3   = (const float*)d_in[3];
    const float* w4   = (const float*)d_in[4];
    const float* lo_w = (const float*)d_in[5];
    const float* lo_b = (const float*)d_in[6];
    float* out = (float*)d_out;

    const int f3_smem = 12688 * 4;  // 50752 bytes
    cudaFuncSetAttribute(f3_inv, cudaFuncAttributeMaxDynamicSharedMemorySize, f3_smem);

    kw_prep<<<576, 256>>>(w1, w2, w3, w4);
    k1_fft_t<<<4096, 128>>>(x);
    k2_fft_y<<<1024, 96>>>();
    k3_fft_x<<<512, 288>>>();
    k4_mix<<<NFREQ/4, 512>>>();
    k5_ifft_x<<<768, 256>>>();
    f3_inv<<<512, 256, f3_smem>>>(lo_w, lo_b, out);
}

// round 10
// speedup vs baseline: 1.0520x; 1.0520x over previous
#include <cuda_runtime.h>
#include <math.h>

#define BB 8
#define CH 16
#define NFREQ (24*24*12)   // 6912

// Scratch
__device__ float2 g_bufA[BB*CH*64*64*12];   // [bc][ix][iy][kt] (fwd only)
__device__ float2 g_bufB[BB*CH*64*24*12];   // [bc][ix][kyi][kt] fwd / [bo][ix][kyi][kt] inv
__device__ float2 g_XF2[NFREQ*128];         // [f][bc]
__device__ float2 g_OF2[NFREQ*128];         // [f][bc]
__device__ float2 g_WT[NFREQ*256];          // [f][i*16+o]

// ---------------------------------------------------------------------------
// KW: weight transpose into frequency-major layout, tiled through smem so both
// global reads and writes are coalesced. Block = (kxi,kyi), 256 threads.
// ---------------------------------------------------------------------------
__global__ void kw_prep(const float* __restrict__ w1, const float* __restrict__ w2,
                        const float* __restrict__ w3, const float* __restrict__ w4) {
    __shared__ float2 sW[12][258];
    int bidx = blockIdx.x;                  // kxi*24 + kyi
    int kxi = bidx / 24, kyi = bidx % 24;
    const float* w = (kxi < 12) ? ((kyi < 12) ? w1 : w3)
                                : ((kyi < 12) ? w2 : w4);
    int kxp = kxi % 12, kyp = kyi % 12;
    int tid = threadIdx.x;                  // 256
    long base = ((long)kxp * 12 + kyp) * 12;
    for (int e = tid; e < 3072; e += 256) {
        int r = e / 12, kt = e % 12;        // read 12 contiguous float2 per r
        sW[kt][r] = ((const float2*)w)[(long)r * 1728 + base + kt];
    }
    __syncthreads();
    long f0 = (long)kxi * 288 + kyi * 12;
    for (int e = tid; e < 3072; e += 256) {
        int kt = e / 256, r = e % 256;      // write 256 contiguous float2 per kt
        g_WT[(f0 + kt) * 256 + r] = sW[kt][r];
    }
}

// ---------------------------------------------------------------------------
// K1: real t-DFT 64 -> 12 modes, +32 parity pairing. 1 thread = 1 row.
// ---------------------------------------------------------------------------
__global__ void k1_fft_t(const float* __restrict__ x) {
    __shared__ float  xs[128][65];
    __shared__ __align__(16) float2 twm[32][12];
    int tid = threadIdx.x;  // 128
    for (int e = tid; e < 384; e += 128) {
        int tp = e / 12, k = e % 12;
        float sn, cs; sincospif((float)((tp * k) & 63) / 32.0f, &sn, &cs);
        twm[tp][k] = make_float2(cs, sn);
    }
    long base = (long)blockIdx.x * 128 * 64;
    const float4* xv = (const float4*)(x + base);
    for (int e = tid; e < 2048; e += 128) {
        float4 v = xv[e];
        int row = e >> 4, col = (e & 15) << 2;
        xs[row][col] = v.x; xs[row][col+1] = v.y; xs[row][col+2] = v.z; xs[row][col+3] = v.w;
    }
    __syncthreads();

    float re[12], im[12];
    #pragma unroll
    for (int k = 0; k < 12; k++) { re[k] = 0.f; im[k] = 0.f; }

    #pragma unroll 4
    for (int tp = 0; tp < 32; tp++) {
        float a = xs[tid][tp], b = xs[tid][tp + 32];
        float ve = a + b, vo = a - b;
        const float4* tp4 = (const float4*)&twm[tp][0];
        #pragma unroll
        for (int j = 0; j < 6; j++) {
            float4 w = tp4[j];
            re[2*j]   = fmaf(ve, w.x, re[2*j]);
            im[2*j]   = fmaf(-ve, w.y, im[2*j]);
            re[2*j+1] = fmaf(vo, w.z, re[2*j+1]);
            im[2*j+1] = fmaf(-vo, w.w, im[2*j+1]);
        }
    }
    float4* ob = (float4*)&g_bufA[((long)blockIdx.x * 128 + tid) * 12];
    #pragma unroll
    for (int j = 0; j < 6; j++)
        ob[j] = make_float4(re[2*j], im[2*j], re[2*j+1], im[2*j+1]);
}

// ---------------------------------------------------------------------------
// K2: complex y-DFT 64 -> 24 modes, +32 parity pairing. Conflict-free padded
// smem (per-ixl stride 389 float2). Block=(bc, 8 ix), 96 thr.
// ---------------------------------------------------------------------------
__global__ void k2_fft_y() {
    __shared__ float2 sIn[8 * 389 + 3];
    __shared__ __align__(16) float2 twy[32][24];
    int tid = threadIdx.x;  // 96
    for (int e = tid; e < 768; e += 96) {
        int yp = e / 24, kyi = e % 24;
        int ky = (kyi < 12) ? kyi : kyi + 40;
        float sn, cs; sincospif((float)((ky * yp) & 63) / 32.0f, &sn, &cs);
        twy[yp][kyi] = make_float2(cs, sn);
    }
    int bc  = blockIdx.x >> 3;
    int ixg = (blockIdx.x & 7) * 8;
    int ixl = tid / 12, kt = tid % 12;

    float ar[24], ai[24];
    #pragma unroll
    for (int i = 0; i < 24; i++) { ar[i] = 0.f; ai[i] = 0.f; }

    for (int cy = 0; cy < 2; cy++) {
        __syncthreads();
        for (int e = tid; e < 3072; e += 96) {
            int il = e / 384, rem = e % 384, h = rem / 192, r2 = rem % 192;
            sIn[il * 389 + h * 192 + r2] =
                g_bufA[((long)(bc*64 + ixg + il) * 64 + cy*16 + h*32) * 12 + r2];
        }
        __syncthreads();
        const float2* sRow = &sIn[ixl * 389 + kt];
        for (int yy = 0; yy < 16; yy++) {
            int yp = cy * 16 + yy;
            float2 v1 = sRow[yy * 12];
            float2 v2 = sRow[192 + yy * 12];
            float vex = v1.x + v2.x, vey = v1.y + v2.y;
            float vox = v1.x - v2.x, voy = v1.y - v2.y;
            const float4* tp4 = (const float4*)&twy[yp][0];
            #pragma unroll
            for (int j = 0; j < 12; j++) {
                float4 w = tp4[j];
                ar[2*j]   = fmaf(vex, w.x, fmaf( vey, w.y, ar[2*j]));
                ai[2*j]   = fmaf(vey, w.x, fmaf(-vex, w.y, ai[2*j]));
                ar[2*j+1] = fmaf(vox, w.z, fmaf( voy, w.w, ar[2*j+1]));
                ai[2*j+1] = fmaf(voy, w.z, fmaf(-vox, w.w, ai[2*j+1]));
            }
        }
    }
    long obase = ((long)(bc * 64 + ixg + ixl) * 24) * 12 + kt;
    #pragma unroll
    for (int kyi = 0; kyi < 24; kyi++)
        g_bufB[obase + kyi * 12] = make_float2(ar[kyi], ai[kyi]);
}

// ---------------------------------------------------------------------------
// K3: complex x-DFT 64 -> 24 modes, +32 parity pairing. Direct coalesced
// global streaming (no smem staging, no syncs). Block = bc, 288 threads.
// Consecutive tids read consecutive float2 -> perfectly coalesced, L2-hot.
// ---------------------------------------------------------------------------
__global__ void k3_fft_x() {
    __shared__ __align__(16) float2 twx[32][24];
    int tid = threadIdx.x;  // 288
    for (int e = tid; e < 768; e += 288) {
        int xp = e / 24, kxi = e % 24;
        int kx = (kxi < 12) ? kxi : kxi + 40;
        float sn, cs; sincospif((float)((kx * xp) & 63) / 32.0f, &sn, &cs);
        twx[xp][kxi] = make_float2(cs, sn);
    }
    int bc = blockIdx.x;
    __syncthreads();

    float ar[24], ai[24];
    #pragma unroll
    for (int i = 0; i < 24; i++) { ar[i] = 0.f; ai[i] = 0.f; }

    const float2* __restrict__ src = &g_bufB[(long)bc * 64 * 288];
    #pragma unroll 4
    for (int xp = 0; xp < 32; xp++) {
        float2 v1 = src[xp * 288 + tid];
        float2 v2 = src[(xp + 32) * 288 + tid];
        float vex = v1.x + v2.x, vey = v1.y + v2.y;
        float vox = v1.x - v2.x, voy = v1.y - v2.y;
        const float4* tp4 = (const float4*)&twx[xp][0];
        #pragma unroll
        for (int j = 0; j < 12; j++) {
            float4 w = tp4[j];
            ar[2*j]   = fmaf(vex, w.x, fmaf( vey, w.y, ar[2*j]));
            ai[2*j]   = fmaf(vey, w.x, fmaf(-vex, w.y, ai[2*j]));
            ar[2*j+1] = fmaf(vox, w.z, fmaf( voy, w.w, ar[2*j+1]));
            ai[2*j+1] = fmaf(voy, w.z, fmaf(-vox, w.w, ai[2*j+1]));
        }
    }
    #pragma unroll
    for (int kxi = 0; kxi < 24; kxi++)
        g_XF2[(long)(kxi * 288 + tid) * 128 + bc] = make_float2(ar[kxi], ai[kxi]);
}

// ---------------------------------------------------------------------------
// K4: per-frequency 16x16 complex mix. 4 freqs/block, 512 threads.
// ---------------------------------------------------------------------------
__global__ void k4_mix() {
    __shared__ __align__(16) float2 ws[4][256];
    __shared__ float2 xs[4][128];
    int tid  = threadIdx.x;            // 512
    int slot = tid >> 7, st = tid & 127;
    int f = blockIdx.x * 4 + slot;
    {
        const float4* wp = (const float4*)&g_WT[(long)f * 256];
        ((float4*)&ws[slot][0])[st] = wp[st];
    }
    xs[slot][st] = g_XF2[(long)f * 128 + st];
    __syncthreads();
    int b = st >> 4, o = st & 15;
    float re = 0.f, im = 0.f;
    #pragma unroll
    for (int i = 0; i < 16; i++) {
        float2 a  = xs[slot][b * 16 + i];
        float2 wv = ws[slot][i * 16 + o];
        re = fmaf(a.x, wv.x, fmaf(-a.y, wv.y, re));
        im = fmaf(a.x, wv.y, fmaf( a.y, wv.x, im));
    }
    g_OF2[(long)f * 128 + st] = make_float2(re, im);
}

// ---------------------------------------------------------------------------
// K5: inverse x-DFT 24 -> 64 with conjugate-mode pairing (S/D in smem).
// Block = (bo, 4 kyi), 256 thr = (kslot, ix).
// ---------------------------------------------------------------------------
__global__ void k5_ifft_x() {
    __shared__ __align__(16) float4 sSD[4][11][12];
    __shared__ __align__(16) float2 sV0[4][12];
    __shared__ __align__(16) float2 sV12[4][12];
    __shared__ float2 tw[64];
    int tid = threadIdx.x;  // 256
    if (tid < 64) {
        float sn, cs; sincospif((float)tid / 32.0f, &sn, &cs);
        tw[tid] = make_float2(cs, sn);
    }
    int bo  = blockIdx.x / 6;
    int kyg = (blockIdx.x % 6) * 4;
    if (tid < 48) {
        int ks = tid / 12, kt = tid % 12;
        sV0[ks][kt]  = g_OF2[(long)(0 * 288 + (kyg + ks) * 12 + kt) * 128 + bo];
        sV12[ks][kt] = g_OF2[(long)(12 * 288 + (kyg + ks) * 12 + kt) * 128 + bo];
    }
    for (int e = tid; e < 528; e += 256) {
        int ks = e / 132, r = e % 132, kp = r / 12 + 1, kt = r % 12;
        float2 v1 = g_OF2[(long)(kp * 288 + (kyg + ks) * 12 + kt) * 128 + bo];
        float2 v2 = g_OF2[(long)((24 - kp) * 288 + (kyg + ks) * 12 + kt) * 128 + bo];
        sSD[ks][kp - 1][kt] = make_float4(v1.x + v2.x, v1.y + v2.y, v1.x - v2.x, v1.y - v2.y);
    }
    __syncthreads();
    int kslot = tid >> 6, ix = tid & 63;

    float ar[12], ai[12];
    {
        const float4* v0 = (const float4*)&sV0[kslot][0];
        #pragma unroll
        for (int j = 0; j < 6; j++) {
            float4 v = v0[j];
            ar[2*j] = v.x; ai[2*j] = v.y; ar[2*j+1] = v.z; ai[2*j+1] = v.w;
        }
    }
    #pragma unroll
    for (int kp = 1; kp < 12; kp++) {
        float2 w = tw[(kp * ix) & 63];
        #pragma unroll
        for (int kt = 0; kt < 12; kt++) {
            float4 sd = sSD[kslot][kp - 1][kt];
            ar[kt] = fmaf(sd.x, w.x, fmaf(-sd.w, w.y, ar[kt]));
            ai[kt] = fmaf(sd.z, w.y, fmaf( sd.y, w.x, ai[kt]));
        }
    }
    {
        float2 w = tw[(52 * ix) & 63];
        const float4* vp = (const float4*)&sV12[kslot][0];
        #pragma unroll
        for (int j = 0; j < 6; j++) {
            float4 v = vp[j];
            ar[2*j]   = fmaf(v.x, w.x, fmaf(-v.y, w.y, ar[2*j]));
            ai[2*j]   = fmaf(v.x, w.y, fmaf( v.y, w.x, ai[2*j]));
            ar[2*j+1] = fmaf(v.z, w.x, fmaf(-v.w, w.y, ar[2*j+1]));
            ai[2*j+1] = fmaf(v.z, w.y, fmaf( v.w, w.x, ai[2*j+1]));
        }
    }
    float4* ob = (float4*)&g_bufB[((long)(bo * 64 + ix) * 24 + kyg + kslot) * 12];
    #pragma unroll
    for (int j = 0; j < 6; j++)
        ob[j] = make_float4(ar[2*j], ai[2*j], ar[2*j+1], ai[2*j+1]);
}

// ---------------------------------------------------------------------------
// F3: fused inverse y-DFT (conj-paired S/D) + inverse real t-DFT (t/t+32
// parity) + ReLU + 16x16 channel mix + bias. Block = (b,ix), 256 threads.
// ---------------------------------------------------------------------------
__global__ void f3_inv(const float* __restrict__ lo_w, const float* __restrict__ lo_b,
                       float* __restrict__ out) {
    extern __shared__ __align__(16) float sm[];
    float4* sSD  = (float4*)sm;                    // [16][11][12]  floats [0,8448)
    float2* H    = (float2*)(sm + 8448);           // [16][8][12]   floats [8448,11520)
    float2* sV0  = (float2*)(sm + 11520);          // [16][12]
    float2* sV12 = (float2*)(sm + 11904);          // [16][12]
    float2* tw   = (float2*)(sm + 12288);          // [64]
    float*  lwT  = sm + 12416;                     // [16][16] c-major
    float*  lb   = sm + 12672;                     // [16]

    int tid = threadIdx.x;  // 256
    if (tid < 64) {
        float sn, cs; sincospif((float)tid / 32.0f, &sn, &cs);
        tw[tid] = make_float2(cs, sn);
    }
    lwT[(tid & 15) * 16 + (tid >> 4)] = lo_w[tid];
    if (tid < 16) lb[tid] = lo_b[tid];

    int b = blockIdx.x >> 6, ixx = blockIdx.x & 63;
    for (int e = tid; e < 192; e += 256) {
        int o = e / 12, kt = e % 12;
        long rbase = ((long)((b*16+o) * 64 + ixx) * 24) * 12;
        sV0[e]  = g_bufB[rbase + kt];
        sV12[e] = g_bufB[rbase + 144 + kt];
    }
    for (int e = tid; e < 2112; e += 256) {
        int o = e / 132, r = e % 132, kp = r / 12 + 1, kt = r % 12;
        long rbase = ((long)((b*16+o) * 64 + ixx) * 24) * 12;
        float2 v1 = g_bufB[rbase + kp * 12 + kt];
        float2 v2 = g_bufB[rbase + (24 - kp) * 12 + kt];
        sSD[e] = make_float4(v1.x + v2.x, v1.y + v2.y, v1.x - v2.x, v1.y - v2.y);
    }
    __syncthreads();

    int iyl = tid >> 5, tp = tid & 31;
    float c2[12], s2[12];
    #pragma unroll
    for (int k = 1; k < 12; k++) {
        float2 w = tw[(k * tp) & 63];
        c2[k] = 2.0f * w.x;
        s2[k] = 2.0f * w.y;
    }
    const float scale = 1.0f / (64.0f * 64.0f * 64.0f);

    for (int cy = 0; cy < 8; cy++) {
        #pragma unroll
        for (int j = 0; j < 6; j++) {
            int e = tid + j * 256;
            int o = e / 96, rem = e % 96;
            int iyA = cy * 8 + rem / 12, kt = rem % 12;
            float2 v0 = sV0[o * 12 + kt];
            float arx = v0.x, aix = v0.y;
            #pragma unroll
            for (int kp = 1; kp < 12; kp++) {
                float2 w = tw[(kp * iyA) & 63];
                float4 sd = sSD[o * 132 + (kp - 1) * 12 + kt];
                arx = fmaf(sd.x, w.x, fmaf(-sd.w, w.y, arx));
                aix = fmaf(sd.z, w.y, fmaf( sd.y, w.x, aix));
            }
            float2 w = tw[(52 * iyA) & 63];
            float2 v12 = sV12[o * 12 + kt];
            arx = fmaf(v12.x, w.x, fmaf(-v12.y, w.y, arx));
            aix = fmaf(v12.x, w.y, fmaf( v12.y, w.x, aix));
            H[(o * 8 + rem / 12) * 12 + kt] = make_float2(arx, aix);
        }
        __syncthreads();

        float acc1[16], acc2[16];
        #pragma unroll
        for (int o = 0; o < 16; o++) { acc1[o] = lb[o]; acc2[o] = lb[o]; }

        #pragma unroll 4
        for (int c = 0; c < 16; c++) {
            const float4* Fp = (const float4*)&H[(c * 8 + iyl) * 12];
            float4 a0 = Fp[0], a1 = Fp[1], a2 = Fp[2], a3 = Fp[3], a4 = Fp[4], a5 = Fp[5];
            float po = fmaf(a0.z, c2[1],  -a0.w * s2[1]);
            float pe = fmaf(a1.x, c2[2],  -a1.y * s2[2]);
            po = fmaf(a1.z, c2[3],  fmaf(-a1.w, s2[3],  po));
            pe = fmaf(a2.x, c2[4],  fmaf(-a2.y, s2[4],  pe));
            po = fmaf(a2.z, c2[5],  fmaf(-a2.w, s2[5],  po));
            pe = fmaf(a3.x, c2[6],  fmaf(-a3.y, s2[6],  pe));
            po = fmaf(a3.z, c2[7],  fmaf(-a3.w, s2[7],  po));
            pe = fmaf(a4.x, c2[8],  fmaf(-a4.y, s2[8],  pe));
            po = fmaf(a4.z, c2[9],  fmaf(-a4.w, s2[9],  po));
            pe = fmaf(a5.x, c2[10], fmaf(-a5.y, s2[10], pe));
            po = fmaf(a5.z, c2[11], fmaf(-a5.w, s2[11], po));
            float base = a0.x + pe;
            float v1 = fmaxf((base + po) * scale, 0.0f);
            float v2 = fmaxf((base - po) * scale, 0.0f);
            const float4* lp = (const float4*)&lwT[c * 16];
            float4 l0 = lp[0], l1 = lp[1], l2 = lp[2], l3 = lp[3];
            acc1[0]  = fmaf(l0.x, v1, acc1[0]);  acc2[0]  = fmaf(l0.x, v2, acc2[0]);
            acc1[1]  = fmaf(l0.y, v1, acc1[1]);  acc2[1]  = fmaf(l0.y, v2, acc2[1]);
            acc1[2]  = fmaf(l0.z, v1, acc1[2]);  acc2[2]  = fmaf(l0.z, v2, acc2[2]);
            acc1[3]  = fmaf(l0.w, v1, acc1[3]);  acc2[3]  = fmaf(l0.w, v2, acc2[3]);
            acc1[4]  = fmaf(l1.x, v1, acc1[4]);  acc2[4]  = fmaf(l1.x, v2, acc2[4]);
            acc1[5]  = fmaf(l1.y, v1, acc1[5]);  acc2[5]  = fmaf(l1.y, v2, acc2[5]);
            acc1[6]  = fmaf(l1.z, v1, acc1[6]);  acc2[6]  = fmaf(l1.z, v2, acc2[6]);
            acc1[7]  = fmaf(l1.w, v1, acc1[7]);  acc2[7]  = fmaf(l1.w, v2, acc2[7]);
            acc1[8]  = fmaf(l2.x, v1, acc1[8]);  acc2[8]  = fmaf(l2.x, v2, acc2[8]);
            acc1[9]  = fmaf(l2.y, v1, acc1[9]);  acc2[9]  = fmaf(l2.y, v2, acc2[9]);
            acc1[10] = fmaf(l2.z, v1, acc1[10]); acc2[10] = fmaf(l2.z, v2, acc2[10]);
            acc1[11] = fmaf(l2.w, v1, acc1[11]); acc2[11] = fmaf(l2.w, v2, acc2[11]);
            acc1[12] = fmaf(l3.x, v1, acc1[12]); acc2[12] = fmaf(l3.x, v2, acc2[12]);
            acc1[13] = fmaf(l3.y, v1, acc1[13]); acc2[13] = fmaf(l3.y, v2, acc2[13]);
            acc1[14] = fmaf(l3.z, v1, acc1[14]); acc2[14] = fmaf(l3.z, v2, acc2[14]);
            acc1[15] = fmaf(l3.w, v1, acc1[15]); acc2[15] = fmaf(l3.w, v2, acc2[15]);
        }

        int iy = cy * 8 + iyl;
        long obase = (long)b * 16 * 262144 + ((long)ixx * 64 + iy) * 64;
        #pragma unroll
        for (int o = 0; o < 16; o++) {
            out[obase + (long)o * 262144 + tp]      = acc1[o];
            out[obase + (long)o * 262144 + tp + 32] = acc2[o];
        }
        __syncthreads();
    }
}

// ---------------------------------------------------------------------------
extern "C" void kernel_launch(void* const* d_in, const int* in_sizes, int n_in,
                              void* d_out, int out_size) {
    const float* x    = (const float*)d_in[0];
    const float* w1   = (const float*)d_in[1];
    const float* w2   = (const float*)d_in[2];
    const float* w3   = (const float*)d_in[3];
    const float* w4   = (const float*)d_in[4];
    const float* lo_w = (const float*)d_in[5];
    const float* lo_b = (const float*)d_in[6];
    float* out = (float*)d_out;

    const int f3_smem = 12688 * 4;  // 50752 bytes
    cudaFuncSetAttribute(f3_inv, cudaFuncAttributeMaxDynamicSharedMemorySize, f3_smem);

    kw_prep<<<576, 256>>>(w1, w2, w3, w4);
    k1_fft_t<<<4096, 128>>>(x);
    k2_fft_y<<<1024, 96>>>();
    k3_fft_x<<<128, 288>>>();
    k4_mix<<<NFREQ/4, 512>>>();
    k5_ifft_x<<<768, 256>>>();
    f3_inv<<<512, 256, f3_smem>>>(lo_w, lo_b, out);
}

// round 11
// speedup vs baseline: 1.0655x; 1.0129x over previous
#include <cuda_runtime.h>
#include <math.h>

#define BB 8
#define CH 16
#define NFREQ (24*24*12)   // 6912

// Scratch
__device__ float2 g_bufA[BB*CH*64*64*12];   // [bc][ix][iy][kt] fwd / [bo][ix][iy][kt] inv
__device__ float2 g_bufB[BB*CH*64*24*12];   // [bc][ix][kyi][kt] fwd / [bo][ix][kyi][kt] inv
__device__ float2 g_XF2[NFREQ*128];         // [f][bc]
__device__ float2 g_OF2[NFREQ*128];         // [f][bc]
__device__ float2 g_WT[NFREQ*256];          // [f][i*16+o]

// ---------------------------------------------------------------------------
// KW: weight transpose into frequency-major layout, tiled through smem so both
// global reads and writes are coalesced. Block = (kxi,kyi), 256 threads.
// ---------------------------------------------------------------------------
__global__ void kw_prep(const float* __restrict__ w1, const float* __restrict__ w2,
                        const float* __restrict__ w3, const float* __restrict__ w4) {
    __shared__ float2 sW[12][258];
    int bidx = blockIdx.x;                  // kxi*24 + kyi
    int kxi = bidx / 24, kyi = bidx % 24;
    const float* w = (kxi < 12) ? ((kyi < 12) ? w1 : w3)
                                : ((kyi < 12) ? w2 : w4);
    int kxp = kxi % 12, kyp = kyi % 12;
    int tid = threadIdx.x;                  // 256
    long base = ((long)kxp * 12 + kyp) * 12;
    for (int e = tid; e < 3072; e += 256) {
        int r = e / 12, kt = e % 12;        // read 12 contiguous float2 per r
        sW[kt][r] = ((const float2*)w)[(long)r * 1728 + base + kt];
    }
    __syncthreads();
    long f0 = (long)kxi * 288 + kyi * 12;
    for (int e = tid; e < 3072; e += 256) {
        int kt = e / 256, r = e % 256;      // write 256 contiguous float2 per kt
        g_WT[(f0 + kt) * 256 + r] = sW[kt][r];
    }
}

// ---------------------------------------------------------------------------
// K1: real t-DFT 64 -> 12 modes, +32 parity pairing. 1 thread = 1 row.
// ---------------------------------------------------------------------------
__global__ void k1_fft_t(const float* __restrict__ x) {
    __shared__ float  xs[128][65];
    __shared__ __align__(16) float2 twm[32][12];
    int tid = threadIdx.x;  // 128
    for (int e = tid; e < 384; e += 128) {
        int tp = e / 12, k = e % 12;
        float sn, cs; sincospif((float)((tp * k) & 63) / 32.0f, &sn, &cs);
        twm[tp][k] = make_float2(cs, sn);
    }
    long base = (long)blockIdx.x * 128 * 64;
    const float4* xv = (const float4*)(x + base);
    for (int e = tid; e < 2048; e += 128) {
        float4 v = xv[e];
        int row = e >> 4, col = (e & 15) << 2;
        xs[row][col] = v.x; xs[row][col+1] = v.y; xs[row][col+2] = v.z; xs[row][col+3] = v.w;
    }
    __syncthreads();

    float re[12], im[12];
    #pragma unroll
    for (int k = 0; k < 12; k++) { re[k] = 0.f; im[k] = 0.f; }

    #pragma unroll 4
    for (int tp = 0; tp < 32; tp++) {
        float a = xs[tid][tp], b = xs[tid][tp + 32];
        float ve = a + b, vo = a - b;
        const float4* tp4 = (const float4*)&twm[tp][0];
        #pragma unroll
        for (int j = 0; j < 6; j++) {
            float4 w = tp4[j];
            re[2*j]   = fmaf(ve, w.x, re[2*j]);
            im[2*j]   = fmaf(-ve, w.y, im[2*j]);
            re[2*j+1] = fmaf(vo, w.z, re[2*j+1]);
            im[2*j+1] = fmaf(-vo, w.w, im[2*j+1]);
        }
    }
    float4* ob = (float4*)&g_bufA[((long)blockIdx.x * 128 + tid) * 12];
    #pragma unroll
    for (int j = 0; j < 6; j++)
        ob[j] = make_float4(re[2*j], im[2*j], re[2*j+1], im[2*j+1]);
}

// ---------------------------------------------------------------------------
// K2: complex y-DFT 64 -> 24 modes, +32 parity pairing. Conflict-free padded
// smem (per-ixl stride 389 float2). Block=(bc, 8 ix), 96 thr=(ixl,kt).
// ---------------------------------------------------------------------------
__global__ void k2_fft_y() {
    __shared__ float2 sIn[8 * 389 + 3];
    __shared__ __align__(16) float2 twy[32][24];
    int tid = threadIdx.x;  // 96
    for (int e = tid; e < 768; e += 96) {
        int yp = e / 24, kyi = e % 24;
        int ky = (kyi < 12) ? kyi : kyi + 40;
        float sn, cs; sincospif((float)((ky * yp) & 63) / 32.0f, &sn, &cs);
        twy[yp][kyi] = make_float2(cs, sn);
    }
    int bc  = blockIdx.x >> 3;
    int ixg = (blockIdx.x & 7) * 8;
    int ixl = tid / 12, kt = tid % 12;

    float ar[24], ai[24];
    #pragma unroll
    for (int i = 0; i < 24; i++) { ar[i] = 0.f; ai[i] = 0.f; }

    for (int cy = 0; cy < 2; cy++) {
        __syncthreads();
        for (int e = tid; e < 3072; e += 96) {
            int il = e / 384, rem = e % 384, h = rem / 192, r2 = rem % 192;
            sIn[il * 389 + h * 192 + r2] =
                g_bufA[((long)(bc*64 + ixg + il) * 64 + cy*16 + h*32) * 12 + r2];
        }
        __syncthreads();
        const float2* sRow = &sIn[ixl * 389 + kt];
        for (int yy = 0; yy < 16; yy++) {
            int yp = cy * 16 + yy;
            float2 v1 = sRow[yy * 12];
            float2 v2 = sRow[192 + yy * 12];
            float vex = v1.x + v2.x, vey = v1.y + v2.y;
            float vox = v1.x - v2.x, voy = v1.y - v2.y;
            const float4* tp4 = (const float4*)&twy[yp][0];
            #pragma unroll
            for (int j = 0; j < 12; j++) {
                float4 w = tp4[j];
                ar[2*j]   = fmaf(vex, w.x, fmaf( vey, w.y, ar[2*j]));
                ai[2*j]   = fmaf(vey, w.x, fmaf(-vex, w.y, ai[2*j]));
                ar[2*j+1] = fmaf(vox, w.z, fmaf( voy, w.w, ar[2*j+1]));
                ai[2*j+1] = fmaf(voy, w.z, fmaf(-vox, w.w, ai[2*j+1]));
            }
        }
    }
    long obase = ((long)(bc * 64 + ixg + ixl) * 24) * 12 + kt;
    #pragma unroll
    for (int kyi = 0; kyi < 24; kyi++)
        g_bufB[obase + kyi * 12] = make_float2(ar[kyi], ai[kyi]);
}

// ---------------------------------------------------------------------------
// K3: complex x-DFT 64 -> 24 modes, +32 parity pairing, smem-staged (R7 form).
// Block = bc, 288 thr = (kyi*12+kt), 24 kxi accums. Writes XF2[f][bc].
// ---------------------------------------------------------------------------
__global__ void k3_fft_x() {
    __shared__ __align__(16) float2 sIn[8][2][288];
    __shared__ __align__(16) float2 twx[32][24];
    int tid = threadIdx.x;  // 288
    for (int e = tid; e < 768; e += 288) {
        int xp = e / 24, kxi = e % 24;
        int kx = (kxi < 12) ? kxi : kxi + 40;
        float sn, cs; sincospif((float)((kx * xp) & 63) / 32.0f, &sn, &cs);
        twx[xp][kxi] = make_float2(cs, sn);
    }
    int bc = blockIdx.x;

    float ar[24], ai[24];
    #pragma unroll
    for (int i = 0; i < 24; i++) { ar[i] = 0.f; ai[i] = 0.f; }

    for (int cx = 0; cx < 4; cx++) {
        __syncthreads();
        for (int e = tid; e < 2304; e += 288) {
            int xl = e / 288, h = (e / 144) & 1, r = e % 144;
            const float4* src = (const float4*)&g_bufB[((long)(bc * 64 + cx*8 + xl + h*32)) * 288];
            ((float4*)&sIn[xl][h][0])[r] = src[r];
        }
        __syncthreads();
        #pragma unroll 2
        for (int xl = 0; xl < 8; xl++) {
            int xp = cx * 8 + xl;
            float2 v1 = sIn[xl][0][tid];
            float2 v2 = sIn[xl][1][tid];
            float vex = v1.x + v2.x, vey = v1.y + v2.y;
            float vox = v1.x - v2.x, voy = v1.y - v2.y;
            const float4* tp4 = (const float4*)&twx[xp][0];
            #pragma unroll
            for (int j = 0; j < 12; j++) {
                float4 w = tp4[j];
                ar[2*j]   = fmaf(vex, w.x, fmaf( vey, w.y, ar[2*j]));
                ai[2*j]   = fmaf(vey, w.x, fmaf(-vex, w.y, ai[2*j]));
                ar[2*j+1] = fmaf(vox, w.z, fmaf( voy, w.w, ar[2*j+1]));
                ai[2*j+1] = fmaf(voy, w.z, fmaf(-vox, w.w, ai[2*j+1]));
            }
        }
    }
    #pragma unroll
    for (int kxi = 0; kxi < 24; kxi++)
        g_XF2[(long)(kxi * 288 + tid) * 128 + bc] = make_float2(ar[kxi], ai[kxi]);
}

// ---------------------------------------------------------------------------
// K4: per-frequency 16x16 complex mix. 4 freqs/block, 512 threads.
// ---------------------------------------------------------------------------
__global__ void k4_mix() {
    __shared__ __align__(16) float2 ws[4][256];
    __shared__ float2 xs[4][128];
    int tid  = threadIdx.x;            // 512
    int slot = tid >> 7, st = tid & 127;
    int f = blockIdx.x * 4 + slot;
    {
        const float4* wp = (const float4*)&g_WT[(long)f * 256];
        ((float4*)&ws[slot][0])[st] = wp[st];
    }
    xs[slot][st] = g_XF2[(long)f * 128 + st];
    __syncthreads();
    int b = st >> 4, o = st & 15;
    float re = 0.f, im = 0.f;
    #pragma unroll
    for (int i = 0; i < 16; i++) {
        float2 a  = xs[slot][b * 16 + i];
        float2 wv = ws[slot][i * 16 + o];
        re = fmaf(a.x, wv.x, fmaf(-a.y, wv.y, re));
        im = fmaf(a.x, wv.y, fmaf( a.y, wv.x, im));
    }
    g_OF2[(long)f * 128 + st] = make_float2(re, im);
}

// ---------------------------------------------------------------------------
// K5: inverse x-DFT 24 -> 64 with conjugate-mode pairing (S/D in smem).
// Block = (bo, 4 kyi), 256 thr = (kslot, ix).
// ---------------------------------------------------------------------------
__global__ void k5_ifft_x() {
    __shared__ __align__(16) float4 sSD[4][11][12];
    __shared__ __align__(16) float2 sV0[4][12];
    __shared__ __align__(16) float2 sV12[4][12];
    __shared__ float2 tw[64];
    int tid = threadIdx.x;  // 256
    if (tid < 64) {
        float sn, cs; sincospif((float)tid / 32.0f, &sn, &cs);
        tw[tid] = make_float2(cs, sn);
    }
    int bo  = blockIdx.x / 6;
    int kyg = (blockIdx.x % 6) * 4;
    if (tid < 48) {
        int ks = tid / 12, kt = tid % 12;
        sV0[ks][kt]  = g_OF2[(long)(0 * 288 + (kyg + ks) * 12 + kt) * 128 + bo];
        sV12[ks][kt] = g_OF2[(long)(12 * 288 + (kyg + ks) * 12 + kt) * 128 + bo];
    }
    for (int e = tid; e < 528; e += 256) {
        int ks = e / 132, r = e % 132, kp = r / 12 + 1, kt = r % 12;
        float2 v1 = g_OF2[(long)(kp * 288 + (kyg + ks) * 12 + kt) * 128 + bo];
        float2 v2 = g_OF2[(long)((24 - kp) * 288 + (kyg + ks) * 12 + kt) * 128 + bo];
        sSD[ks][kp - 1][kt] = make_float4(v1.x + v2.x, v1.y + v2.y, v1.x - v2.x, v1.y - v2.y);
    }
    __syncthreads();
    int kslot = tid >> 6, ix = tid & 63;

    float ar[12], ai[12];
    {
        const float4* v0 = (const float4*)&sV0[kslot][0];
        #pragma unroll
        for (int j = 0; j < 6; j++) {
            float4 v = v0[j];
            ar[2*j] = v.x; ai[2*j] = v.y; ar[2*j+1] = v.z; ai[2*j+1] = v.w;
        }
    }
    #pragma unroll
    for (int kp = 1; kp < 12; kp++) {
        float2 w = tw[(kp * ix) & 63];
        #pragma unroll
        for (int kt = 0; kt < 12; kt++) {
            float4 sd = sSD[kslot][kp - 1][kt];
            ar[kt] = fmaf(sd.x, w.x, fmaf(-sd.w, w.y, ar[kt]));
            ai[kt] = fmaf(sd.z, w.y, fmaf( sd.y, w.x, ai[kt]));
        }
    }
    {
        float2 w = tw[(52 * ix) & 63];
        const float4* vp = (const float4*)&sV12[kslot][0];
        #pragma unroll
        for (int j = 0; j < 6; j++) {
            float4 v = vp[j];
            ar[2*j]   = fmaf(v.x, w.x, fmaf(-v.y, w.y, ar[2*j]));
            ai[2*j]   = fmaf(v.x, w.y, fmaf( v.y, w.x, ai[2*j]));
            ar[2*j+1] = fmaf(v.z, w.x, fmaf(-v.w, w.y, ar[2*j+1]));
            ai[2*j+1] = fmaf(v.z, w.y, fmaf( v.w, w.x, ai[2*j+1]));
        }
    }
    float4* ob = (float4*)&g_bufB[((long)(bo * 64 + ix) * 24 + kyg + kslot) * 12];
    #pragma unroll
    for (int j = 0; j < 6; j++)
        ob[j] = make_float4(ar[2*j], ai[2*j], ar[2*j+1], ai[2*j+1]);
}

// ---------------------------------------------------------------------------
// K6: inverse y-DFT 24 -> 64 with conjugate-mode pairing.
// Block = (bo, 4 ix), 256 thr = (ixslot, iy).
// ---------------------------------------------------------------------------
__global__ void k6_ifft_y() {
    __shared__ __align__(16) float4 sSD[4][11][12];
    __shared__ __align__(16) float2 sV0[4][12];
    __shared__ __align__(16) float2 sV12[4][12];
    __shared__ float2 tw[64];
    int tid = threadIdx.x;  // 256
    if (tid < 64) {
        float sn, cs; sincospif((float)tid / 32.0f, &sn, &cs);
        tw[tid] = make_float2(cs, sn);
    }
    int bo  = blockIdx.x >> 4;
    int ixg = (blockIdx.x & 15) * 4;
    if (tid < 48) {
        int is = tid / 12, kt = tid % 12;
        long rbase = ((long)(bo * 64 + ixg + is) * 24) * 12;
        sV0[is][kt]  = g_bufB[rbase + kt];
        sV12[is][kt] = g_bufB[rbase + 144 + kt];
    }
    for (int e = tid; e < 528; e += 256) {
        int is = e / 132, r = e % 132, kp = r / 12 + 1, kt = r % 12;
        long rbase = ((long)(bo * 64 + ixg + is) * 24) * 12;
        float2 v1 = g_bufB[rbase + kp * 12 + kt];
        float2 v2 = g_bufB[rbase + (24 - kp) * 12 + kt];
        sSD[is][kp - 1][kt] = make_float4(v1.x + v2.x, v1.y + v2.y, v1.x - v2.x, v1.y - v2.y);
    }
    __syncthreads();
    int islot = tid >> 6, iy = tid & 63;

    float ar[12], ai[12];
    {
        const float4* v0 = (const float4*)&sV0[islot][0];
        #pragma unroll
        for (int j = 0; j < 6; j++) {
            float4 v = v0[j];
            ar[2*j] = v.x; ai[2*j] = v.y; ar[2*j+1] = v.z; ai[2*j+1] = v.w;
        }
    }
    #pragma unroll
    for (int kp = 1; kp < 12; kp++) {
        float2 w = tw[(kp * iy) & 63];
        #pragma unroll
        for (int kt = 0; kt < 12; kt++) {
            float4 sd = sSD[islot][kp - 1][kt];
            ar[kt] = fmaf(sd.x, w.x, fmaf(-sd.w, w.y, ar[kt]));
            ai[kt] = fmaf(sd.z, w.y, fmaf( sd.y, w.x, ai[kt]));
        }
    }
    {
        float2 w = tw[(52 * iy) & 63];
        const float4* vp = (const float4*)&sV12[islot][0];
        #pragma unroll
        for (int j = 0; j < 6; j++) {
            float4 v = vp[j];
            ar[2*j]   = fmaf(v.x, w.x, fmaf(-v.y, w.y, ar[2*j]));
            ai[2*j]   = fmaf(v.x, w.y, fmaf( v.y, w.x, ai[2*j]));
            ar[2*j+1] = fmaf(v.z, w.x, fmaf(-v.w, w.y, ar[2*j+1]));
            ai[2*j+1] = fmaf(v.z, w.y, fmaf( v.w, w.x, ai[2*j+1]));
        }
    }
    float4* ob = (float4*)&g_bufA[((long)(bo * 64 + ixg + islot) * 64 + iy) * 12];
    #pragma unroll
    for (int j = 0; j < 6; j++)
        ob[j] = make_float4(ar[2*j], ai[2*j], ar[2*j+1], ai[2*j+1]);
}

// ---------------------------------------------------------------------------
// K7: inverse real t-DFT with t/t+32 parity split + ReLU + 16x16 mix + bias.
// Block = 8 xy-slots x 32 tp = 256 threads; warp == slot (broadcast LDS).
// ---------------------------------------------------------------------------
__global__ void k7_final(const float* __restrict__ lo_w,
                         const float* __restrict__ lo_b,
                         float* __restrict__ out) {
    __shared__ __align__(16) float2 F[8][16][12];
    __shared__ __align__(16) float  lwT[16][16];   // [c][o]
    __shared__ float  lb[16];
    __shared__ float2 tw[64];
    int tid = threadIdx.x;  // 256
    if (tid < 64) {
        float sn, cs; sincospif((float)tid / 32.0f, &sn, &cs);
        tw[tid] = make_float2(cs, sn);
    }
    lwT[tid & 15][tid >> 4] = lo_w[tid];
    if (tid < 16) lb[tid] = lo_b[tid];

    int b   = blockIdx.x >> 9;
    int xy0 = (blockIdx.x & 511) * 8;
    for (int e = tid; e < 768; e += 256) {
        int slot = e / 96, c = (e % 96) / 6, j = e % 6;
        const float4* src = (const float4*)g_bufA + ((long)(b * 16 + c) * 4096 + xy0 + slot) * 6 + j;
        ((float4*)&F[slot][c][0])[j] = *src;
    }
    __syncthreads();

    int slot = tid >> 5, tp = tid & 31;
    float c2[12], s2[12];
    #pragma unroll
    for (int k = 1; k < 12; k++) {
        float2 w = tw[(k * tp) & 63];
        c2[k] = 2.0f * w.x;
        s2[k] = 2.0f * w.y;
    }

    float acc1[16], acc2[16];
    #pragma unroll
    for (int o = 0; o < 16; o++) { acc1[o] = lb[o]; acc2[o] = lb[o]; }

    const float scale = 1.0f / (64.0f * 64.0f * 64.0f);
    #pragma unroll 4
    for (int c = 0; c < 16; c++) {
        const float4* Fp = (const float4*)&F[slot][c][0];
        float4 a0 = Fp[0], a1 = Fp[1], a2 = Fp[2], a3 = Fp[3], a4 = Fp[4], a5 = Fp[5];
        float po = fmaf(a0.z, c2[1],  -a0.w * s2[1]);
        float pe = fmaf(a1.x, c2[2],  -a1.y * s2[2]);
        po = fmaf(a1.z, c2[3],  fmaf(-a1.w, s2[3],  po));
        pe = fmaf(a2.x, c2[4],  fmaf(-a2.y, s2[4],  pe));
        po = fmaf(a2.z, c2[5],  fmaf(-a2.w, s2[5],  po));
        pe = fmaf(a3.x, c2[6],  fmaf(-a3.y, s2[6],  pe));
        po = fmaf(a3.z, c2[7],  fmaf(-a3.w, s2[7],  po));
        pe = fmaf(a4.x, c2[8],  fmaf(-a4.y, s2[8],  pe));
        po = fmaf(a4.z, c2[9],  fmaf(-a4.w, s2[9],  po));
        pe = fmaf(a5.x, c2[10], fmaf(-a5.y, s2[10], pe));
        po = fmaf(a5.z, c2[11], fmaf(-a5.w, s2[11], po));
        float base = a0.x + pe;
        float v1 = fmaxf((base + po) * scale, 0.0f);   // t = tp
        float v2 = fmaxf((base - po) * scale, 0.0f);   // t = tp+32
        const float4* lp = (const float4*)&lwT[c][0];
        float4 l0 = lp[0], l1 = lp[1], l2 = lp[2], l3 = lp[3];
        acc1[0]  = fmaf(l0.x, v1, acc1[0]);  acc2[0]  = fmaf(l0.x, v2, acc2[0]);
        acc1[1]  = fmaf(l0.y, v1, acc1[1]);  acc2[1]  = fmaf(l0.y, v2, acc2[1]);
        acc1[2]  = fmaf(l0.z, v1, acc1[2]);  acc2[2]  = fmaf(l0.z, v2, acc2[2]);
        acc1[3]  = fmaf(l0.w, v1, acc1[3]);  acc2[3]  = fmaf(l0.w, v2, acc2[3]);
        acc1[4]  = fmaf(l1.x, v1, acc1[4]);  acc2[4]  = fmaf(l1.x, v2, acc2[4]);
        acc1[5]  = fmaf(l1.y, v1, acc1[5]);  acc2[5]  = fmaf(l1.y, v2, acc2[5]);
        acc1[6]  = fmaf(l1.z, v1, acc1[6]);  acc2[6]  = fmaf(l1.z, v2, acc2[6]);
        acc1[7]  = fmaf(l1.w, v1, acc1[7]);  acc2[7]  = fmaf(l1.w, v2, acc2[7]);
        acc1[8]  = fmaf(l2.x, v1, acc1[8]);  acc2[8]  = fmaf(l2.x, v2, acc2[8]);
        acc1[9]  = fmaf(l2.y, v1, acc1[9]);  acc2[9]  = fmaf(l2.y, v2, acc2[9]);
        acc1[10] = fmaf(l2.z, v1, acc1[10]); acc2[10] = fmaf(l2.z, v2, acc2[10]);
        acc1[11] = fmaf(l2.w, v1, acc1[11]); acc2[11] = fmaf(l2.w, v2, acc2[11]);
        acc1[12] = fmaf(l3.x, v1, acc1[12]); acc2[12] = fmaf(l3.x, v2, acc2[12]);
        acc1[13] = fmaf(l3.y, v1, acc1[13]); acc2[13] = fmaf(l3.y, v2, acc2[13]);
        acc1[14] = fmaf(l3.z, v1, acc1[14]); acc2[14] = fmaf(l3.z, v2, acc2[14]);
        acc1[15] = fmaf(l3.w, v1, acc1[15]); acc2[15] = fmaf(l3.w, v2, acc2[15]);
    }

    long obase = (long)b * 16 * 262144 + (long)(xy0 + slot) * 64;
    #pragma unroll
    for (int o = 0; o < 16; o++) {
        out[obase + (long)o * 262144 + tp]      = acc1[o];
        out[obase + (long)o * 262144 + tp + 32] = acc2[o];
    }
}

// ---------------------------------------------------------------------------
extern "C" void kernel_launch(void* const* d_in, const int* in_sizes, int n_in,
                              void* d_out, int out_size) {
    const float* x    = (const float*)d_in[0];
    const float* w1   = (const float*)d_in[1];
    const float* w2   = (const float*)d_in[2];
    const float* w3   = (const float*)d_in[3];
    const float* w4   = (const float*)d_in[4];
    const float* lo_w = (const float*)d_in[5];
    const float* lo_b = (const float*)d_in[6];
    float* out = (float*)d_out;

    kw_prep<<<576, 256>>>(w1, w2, w3, w4);
    k1_fft_t<<<4096, 128>>>(x);
    k2_fft_y<<<1024, 96>>>();
    k3_fft_x<<<128, 288>>>();
    k4_mix<<<NFREQ/4, 512>>>();
    k5_ifft_x<<<768, 256>>>();
    k6_ifft_y<<<2048, 256>>>();
    k7_final<<<4096, 256>>>(lo_w, lo_b, out);
}

// round 12
// speedup vs baseline: 1.1074x; 1.0393x over previous
#include <cuda_runtime.h>
#include <math.h>

#define BB 8
#define CH 16
#define NFREQ (24*24*12)   // 6912

// Scratch
__device__ float2 g_bufA[BB*CH*64*64*12];   // [bc][ix][iy][kt] fwd / [bo][ix][iy][kt] inv
__device__ float2 g_bufB[BB*CH*64*24*12];   // [bc][ix][kyi][kt] fwd / [bo][ix][kyi][kt] inv
__device__ float2 g_XF2[NFREQ*128];         // [f][bc]
__device__ float2 g_OF2[NFREQ*128];         // [f][bc]
__device__ float2 g_WT[NFREQ*256];          // [f][i*16+o]

// ---------------------------------------------------------------------------
// K1W: merged kernel. Blocks [0,4096) = K1 (real t-DFT 64->12, parity paired);
// blocks [4096,4672) = KW (weight transpose, independent of k1..k3, runs
// concurrently and is hidden under k1's tail).
// ---------------------------------------------------------------------------
__global__ void k1w(const float* __restrict__ x,
                    const float* __restrict__ w1, const float* __restrict__ w2,
                    const float* __restrict__ w3, const float* __restrict__ w4) {
    __shared__ __align__(16) unsigned char smraw[36352];
    int tid = threadIdx.x;  // 128

    if (blockIdx.x < 4096) {
        // ---- K1: real t-DFT, 1 thread = 1 row ----
        float (*xs)[65] = (float(*)[65])smraw;          // 128*65*4 = 33280 B
        float2* twm = (float2*)(smraw + 33280);         // 32*12*8 = 3072 B
        for (int e = tid; e < 384; e += 128) {
            int tp = e / 12, k = e % 12;
            float sn, cs; sincospif((float)((tp * k) & 63) / 32.0f, &sn, &cs);
            twm[e] = make_float2(cs, sn);
        }
        long base = (long)blockIdx.x * 128 * 64;
        const float4* xv = (const float4*)(x + base);
        for (int e = tid; e < 2048; e += 128) {
            float4 v = xv[e];
            int row = e >> 4, col = (e & 15) << 2;
            xs[row][col] = v.x; xs[row][col+1] = v.y; xs[row][col+2] = v.z; xs[row][col+3] = v.w;
        }
        __syncthreads();

        float re[12], im[12];
        #pragma unroll
        for (int k = 0; k < 12; k++) { re[k] = 0.f; im[k] = 0.f; }

        #pragma unroll 4
        for (int tp = 0; tp < 32; tp++) {
            float a = xs[tid][tp], b = xs[tid][tp + 32];
            float ve = a + b, vo = a - b;
            const float4* tp4 = (const float4*)&twm[tp * 12];
            #pragma unroll
            for (int j = 0; j < 6; j++) {
                float4 w = tp4[j];
                re[2*j]   = fmaf(ve, w.x, re[2*j]);
                im[2*j]   = fmaf(-ve, w.y, im[2*j]);
                re[2*j+1] = fmaf(vo, w.z, re[2*j+1]);
                im[2*j+1] = fmaf(-vo, w.w, im[2*j+1]);
            }
        }
        float4* ob = (float4*)&g_bufA[((long)blockIdx.x * 128 + tid) * 12];
        #pragma unroll
        for (int j = 0; j < 6; j++)
            ob[j] = make_float4(re[2*j], im[2*j], re[2*j+1], im[2*j+1]);
    } else {
        // ---- KW: weight transpose, tiled through smem ----
        float2 (*sW)[258] = (float2(*)[258])smraw;      // 12*258*8 = 24768 B
        int bidx = blockIdx.x - 4096;                   // kxi*24 + kyi
        int kxi = bidx / 24, kyi = bidx % 24;
        const float* w = (kxi < 12) ? ((kyi < 12) ? w1 : w3)
                                    : ((kyi < 12) ? w2 : w4);
        int kxp = kxi % 12, kyp = kyi % 12;
        long base = ((long)kxp * 12 + kyp) * 12;
        for (int e = tid; e < 3072; e += 128) {
            int r = e / 12, kt = e % 12;
            sW[kt][r] = ((const float2*)w)[(long)r * 1728 + base + kt];
        }
        __syncthreads();
        long f0 = (long)kxi * 288 + kyi * 12;
        for (int e = tid; e < 3072; e += 128) {
            int kt = e / 256, r = e % 256;
            g_WT[(f0 + kt) * 256 + r] = sW[kt][r];
        }
    }
}

// ---------------------------------------------------------------------------
// K2: complex y-DFT 64 -> 24 modes, +32 parity pairing. Conflict-free padded
// smem (per-ixl stride 390 float2, even -> float4 staging). 96 thr=(ixl,kt).
// ---------------------------------------------------------------------------
__global__ void k2_fft_y() {
    __shared__ __align__(16) float2 sIn[8 * 390];
    __shared__ __align__(16) float2 twy[32][24];
    int tid = threadIdx.x;  // 96
    for (int e = tid; e < 768; e += 96) {
        int yp = e / 24, kyi = e % 24;
        int ky = (kyi < 12) ? kyi : kyi + 40;
        float sn, cs; sincospif((float)((ky * yp) & 63) / 32.0f, &sn, &cs);
        twy[yp][kyi] = make_float2(cs, sn);
    }
    int bc  = blockIdx.x >> 3;
    int ixg = (blockIdx.x & 7) * 8;
    int ixl = tid / 12, kt = tid % 12;

    float ar[24], ai[24];
    #pragma unroll
    for (int i = 0; i < 24; i++) { ar[i] = 0.f; ai[i] = 0.f; }

    for (int cy = 0; cy < 2; cy++) {
        __syncthreads();
        for (int e = tid; e < 1536; e += 96) {
            int il = e / 192, rem = e % 192, hh = rem / 96, r4 = rem % 96;
            const float4* src = (const float4*)&g_bufA[((long)(bc*64 + ixg + il) * 64 + cy*16 + hh*32) * 12];
            ((float4*)&sIn[il * 390 + hh * 192])[r4] = src[r4];
        }
        __syncthreads();
        const float2* sRow = &sIn[ixl * 390 + kt];
        for (int yy = 0; yy < 16; yy++) {
            int yp = cy * 16 + yy;
            float2 v1 = sRow[yy * 12];
            float2 v2 = sRow[192 + yy * 12];
            float vex = v1.x + v2.x, vey = v1.y + v2.y;
            float vox = v1.x - v2.x, voy = v1.y - v2.y;
            const float4* tp4 = (const float4*)&twy[yp][0];
            #pragma unroll
            for (int j = 0; j < 12; j++) {
                float4 w = tp4[j];
                ar[2*j]   = fmaf(vex, w.x, fmaf( vey, w.y, ar[2*j]));
                ai[2*j]   = fmaf(vey, w.x, fmaf(-vex, w.y, ai[2*j]));
                ar[2*j+1] = fmaf(vox, w.z, fmaf( voy, w.w, ar[2*j+1]));
                ai[2*j+1] = fmaf(voy, w.z, fmaf(-vox, w.w, ai[2*j+1]));
            }
        }
    }
    long obase = ((long)(bc * 64 + ixg + ixl) * 24) * 12 + kt;
    #pragma unroll
    for (int kyi = 0; kyi < 24; kyi++)
        g_bufB[obase + kyi * 12] = make_float2(ar[kyi], ai[kyi]);
}

// ---------------------------------------------------------------------------
// K3: complex x-DFT 64 -> 24 modes, +32 parity pairing, kyi-split.
// Block = (bc, kyi-half) -> grid 256 (all SMs busy), 144 thr = (kyil,kt).
// Reduction over x stays block-local: no partial buffers, same total traffic.
// ---------------------------------------------------------------------------
__global__ void k3_fft_x() {
    __shared__ __align__(16) float2 sIn[8][2][144];
    __shared__ __align__(16) float2 twx[32][24];
    int tid = threadIdx.x;  // 144
    for (int e = tid; e < 768; e += 144) {
        int xp = e / 24, kxi = e % 24;
        int kx = (kxi < 12) ? kxi : kxi + 40;
        float sn, cs; sincospif((float)((kx * xp) & 63) / 32.0f, &sn, &cs);
        twx[xp][kxi] = make_float2(cs, sn);
    }
    int bc = blockIdx.x >> 1, h = blockIdx.x & 1;

    float ar[24], ai[24];
    #pragma unroll
    for (int i = 0; i < 24; i++) { ar[i] = 0.f; ai[i] = 0.f; }

    for (int cx = 0; cx < 4; cx++) {
        __syncthreads();
        for (int e = tid; e < 1152; e += 144) {
            int xl = e / 144, rem = e % 144, hh = rem / 72, r4 = rem % 72;
            const float4* src = (const float4*)&g_bufB[((long)(bc * 64 + cx*8 + xl + hh*32)) * 288 + h * 144];
            ((float4*)&sIn[xl][hh][0])[r4] = src[r4];
        }
        __syncthreads();
        #pragma unroll 2
        for (int xl = 0; xl < 8; xl++) {
            int xp = cx * 8 + xl;
            float2 v1 = sIn[xl][0][tid];
            float2 v2 = sIn[xl][1][tid];
            float vex = v1.x + v2.x, vey = v1.y + v2.y;
            float vox = v1.x - v2.x, voy = v1.y - v2.y;
            const float4* tp4 = (const float4*)&twx[xp][0];
            #pragma unroll
            for (int j = 0; j < 12; j++) {
                float4 w = tp4[j];
                ar[2*j]   = fmaf(vex, w.x, fmaf( vey, w.y, ar[2*j]));
                ai[2*j]   = fmaf(vey, w.x, fmaf(-vex, w.y, ai[2*j]));
                ar[2*j+1] = fmaf(vox, w.z, fmaf( voy, w.w, ar[2*j+1]));
                ai[2*j+1] = fmaf(voy, w.z, fmaf(-vox, w.w, ai[2*j+1]));
            }
        }
    }
    #pragma unroll
    for (int kxi = 0; kxi < 24; kxi++)
        g_XF2[(long)(kxi * 288 + h * 144 + tid) * 128 + bc] = make_float2(ar[kxi], ai[kxi]);
}

// ---------------------------------------------------------------------------
// K4: per-frequency 16x16 complex mix. 4 freqs/block, 512 threads.
// ---------------------------------------------------------------------------
__global__ void k4_mix() {
    __shared__ __align__(16) float2 ws[4][256];
    __shared__ float2 xs[4][128];
    int tid  = threadIdx.x;            // 512
    int slot = tid >> 7, st = tid & 127;
    int f = blockIdx.x * 4 + slot;
    {
        const float4* wp = (const float4*)&g_WT[(long)f * 256];
        ((float4*)&ws[slot][0])[st] = wp[st];
    }
    xs[slot][st] = g_XF2[(long)f * 128 + st];
    __syncthreads();
    int b = st >> 4, o = st & 15;
    float re = 0.f, im = 0.f;
    #pragma unroll
    for (int i = 0; i < 16; i++) {
        float2 a  = xs[slot][b * 16 + i];
        float2 wv = ws[slot][i * 16 + o];
        re = fmaf(a.x, wv.x, fmaf(-a.y, wv.y, re));
        im = fmaf(a.x, wv.y, fmaf( a.y, wv.x, im));
    }
    g_OF2[(long)f * 128 + st] = make_float2(re, im);
}

// ---------------------------------------------------------------------------
// K5: inverse x-DFT 24 -> 64 with conjugate-mode pairing (S/D in smem).
// Block = (bo, 4 kyi), 256 thr = (kslot, ix).
// ---------------------------------------------------------------------------
__global__ void k5_ifft_x() {
    __shared__ __align__(16) float4 sSD[4][11][12];
    __shared__ __align__(16) float2 sV0[4][12];
    __shared__ __align__(16) float2 sV12[4][12];
    __shared__ float2 tw[64];
    int tid = threadIdx.x;  // 256
    if (tid < 64) {
        float sn, cs; sincospif((float)tid / 32.0f, &sn, &cs);
        tw[tid] = make_float2(cs, sn);
    }
    int bo  = blockIdx.x / 6;
    int kyg = (blockIdx.x % 6) * 4;
    if (tid < 48) {
        int ks = tid / 12, kt = tid % 12;
        sV0[ks][kt]  = g_OF2[(long)(0 * 288 + (kyg + ks) * 12 + kt) * 128 + bo];
        sV12[ks][kt] = g_OF2[(long)(12 * 288 + (kyg + ks) * 12 + kt) * 128 + bo];
    }
    for (int e = tid; e < 528; e += 256) {
        int ks = e / 132, r = e % 132, kp = r / 12 + 1, kt = r % 12;
        float2 v1 = g_OF2[(long)(kp * 288 + (kyg + ks) * 12 + kt) * 128 + bo];
        float2 v2 = g_OF2[(long)((24 - kp) * 288 + (kyg + ks) * 12 + kt) * 128 + bo];
        sSD[ks][kp - 1][kt] = make_float4(v1.x + v2.x, v1.y + v2.y, v1.x - v2.x, v1.y - v2.y);
    }
    __syncthreads();
    int kslot = tid >> 6, ix = tid & 63;

    float ar[12], ai[12];
    {
        const float4* v0 = (const float4*)&sV0[kslot][0];
        #pragma unroll
        for (int j = 0; j < 6; j++) {
            float4 v = v0[j];
            ar[2*j] = v.x; ai[2*j] = v.y; ar[2*j+1] = v.z; ai[2*j+1] = v.w;
        }
    }
    #pragma unroll
    for (int kp = 1; kp < 12; kp++) {
        float2 w = tw[(kp * ix) & 63];
        #pragma unroll
        for (int kt = 0; kt < 12; kt++) {
            float4 sd = sSD[kslot][kp - 1][kt];
            ar[kt] = fmaf(sd.x, w.x, fmaf(-sd.w, w.y, ar[kt]));
            ai[kt] = fmaf(sd.z, w.y, fmaf( sd.y, w.x, ai[kt]));
        }
    }
    {
        float2 w = tw[(52 * ix) & 63];
        const float4* vp = (const float4*)&sV12[kslot][0];
        #pragma unroll
        for (int j = 0; j < 6; j++) {
            float4 v = vp[j];
            ar[2*j]   = fmaf(v.x, w.x, fmaf(-v.y, w.y, ar[2*j]));
            ai[2*j]   = fmaf(v.x, w.y, fmaf( v.y, w.x, ai[2*j]));
            ar[2*j+1] = fmaf(v.z, w.x, fmaf(-v.w, w.y, ar[2*j+1]));
            ai[2*j+1] = fmaf(v.z, w.y, fmaf( v.w, w.x, ai[2*j+1]));
        }
    }
    float4* ob = (float4*)&g_bufB[((long)(bo * 64 + ix) * 24 + kyg + kslot) * 12];
    #pragma unroll
    for (int j = 0; j < 6; j++)
        ob[j] = make_float4(ar[2*j], ai[2*j], ar[2*j+1], ai[2*j+1]);
}

// ---------------------------------------------------------------------------
// K6: inverse y-DFT 24 -> 64 with conjugate-mode pairing.
// Block = (bo, 4 ix), 256 thr = (ixslot, iy).
// ---------------------------------------------------------------------------
__global__ void k6_ifft_y() {
    __shared__ __align__(16) float4 sSD[4][11][12];
    __shared__ __align__(16) float2 sV0[4][12];
    __shared__ __align__(16) float2 sV12[4][12];
    __shared__ float2 tw[64];
    int tid = threadIdx.x;  // 256
    if (tid < 64) {
        float sn, cs; sincospif((float)tid / 32.0f, &sn, &cs);
        tw[tid] = make_float2(cs, sn);
    }
    int bo  = blockIdx.x >> 4;
    int ixg = (blockIdx.x & 15) * 4;
    if (tid < 48) {
        int is = tid / 12, kt = tid % 12;
        long rbase = ((long)(bo * 64 + ixg + is) * 24) * 12;
        sV0[is][kt]  = g_bufB[rbase + kt];
        sV12[is][kt] = g_bufB[rbase + 144 + kt];
    }
    for (int e = tid; e < 528; e += 256) {
        int is = e / 132, r = e % 132, kp = r / 12 + 1, kt = r % 12;
        long rbase = ((long)(bo * 64 + ixg + is) * 24) * 12;
        float2 v1 = g_bufB[rbase + kp * 12 + kt];
        float2 v2 = g_bufB[rbase + (24 - kp) * 12 + kt];
        sSD[is][kp - 1][kt] = make_float4(v1.x + v2.x, v1.y + v2.y, v1.x - v2.x, v1.y - v2.y);
    }
    __syncthreads();
    int islot = tid >> 6, iy = tid & 63;

    float ar[12], ai[12];
    {
        const float4* v0 = (const float4*)&sV0[islot][0];
        #pragma unroll
        for (int j = 0; j < 6; j++) {
            float4 v = v0[j];
            ar[2*j] = v.x; ai[2*j] = v.y; ar[2*j+1] = v.z; ai[2*j+1] = v.w;
        }
    }
    #pragma unroll
    for (int kp = 1; kp < 12; kp++) {
        float2 w = tw[(kp * iy) & 63];
        #pragma unroll
        for (int kt = 0; kt < 12; kt++) {
            float4 sd = sSD[islot][kp - 1][kt];
            ar[kt] = fmaf(sd.x, w.x, fmaf(-sd.w, w.y, ar[kt]));
            ai[kt] = fmaf(sd.z, w.y, fmaf( sd.y, w.x, ai[kt]));
        }
    }
    {
        float2 w = tw[(52 * iy) & 63];
        const float4* vp = (const float4*)&sV12[islot][0];
        #pragma unroll
        for (int j = 0; j < 6; j++) {
            float4 v = vp[j];
            ar[2*j]   = fmaf(v.x, w.x, fmaf(-v.y, w.y, ar[2*j]));
            ai[2*j]   = fmaf(v.x, w.y, fmaf( v.y, w.x, ai[2*j]));
            ar[2*j+1] = fmaf(v.z, w.x, fmaf(-v.w, w.y, ar[2*j+1]));
            ai[2*j+1] = fmaf(v.z, w.y, fmaf( v.w, w.x, ai[2*j+1]));
        }
    }
    float4* ob = (float4*)&g_bufA[((long)(bo * 64 + ixg + islot) * 64 + iy) * 12];
    #pragma unroll
    for (int j = 0; j < 6; j++)
        ob[j] = make_float4(ar[2*j], ai[2*j], ar[2*j+1], ai[2*j+1]);
}

// ---------------------------------------------------------------------------
// K7: inverse real t-DFT with t/t+32 parity split + ReLU + 16x16 mix + bias.
// Block = 8 xy-slots x 32 tp = 256 threads; warp == slot (broadcast LDS).
// ---------------------------------------------------------------------------
__global__ void k7_final(const float* __restrict__ lo_w,
                         const float* __restrict__ lo_b,
                         float* __restrict__ out) {
    __shared__ __align__(16) float2 F[8][16][12];
    __shared__ __align__(16) float  lwT[16][16];   // [c][o]
    __shared__ float  lb[16];
    __shared__ float2 tw[64];
    int tid = threadIdx.x;  // 256
    if (tid < 64) {
        float sn, cs; sincospif((float)tid / 32.0f, &sn, &cs);
        tw[tid] = make_float2(cs, sn);
    }
    lwT[tid & 15][tid >> 4] = lo_w[tid];
    if (tid < 16) lb[tid] = lo_b[tid];

    int b   = blockIdx.x >> 9;
    int xy0 = (blockIdx.x & 511) * 8;
    for (int e = tid; e < 768; e += 256) {
        int slot = e / 96, c = (e % 96) / 6, j = e % 6;
        const float4* src = (const float4*)g_bufA + ((long)(b * 16 + c) * 4096 + xy0 + slot) * 6 + j;
        ((float4*)&F[slot][c][0])[j] = *src;
    }
    __syncthreads();

    int slot = tid >> 5, tp = tid & 31;
    float c2[12], s2[12];
    #pragma unroll
    for (int k = 1; k < 12; k++) {
        float2 w = tw[(k * tp) & 63];
        c2[k] = 2.0f * w.x;
        s2[k] = 2.0f * w.y;
    }

    float acc1[16], acc2[16];
    #pragma unroll
    for (int o = 0; o < 16; o++) { acc1[o] = lb[o]; acc2[o] = lb[o]; }

    const float scale = 1.0f / (64.0f * 64.0f * 64.0f);
    #pragma unroll 4
    for (int c = 0; c < 16; c++) {
        const float4* Fp = (const float4*)&F[slot][c][0];
        float4 a0 = Fp[0], a1 = Fp[1], a2 = Fp[2], a3 = Fp[3], a4 = Fp[4], a5 = Fp[5];
        float po = fmaf(a0.z, c2[1],  -a0.w * s2[1]);
        float pe = fmaf(a1.x, c2[2],  -a1.y * s2[2]);
        po = fmaf(a1.z, c2[3],  fmaf(-a1.w, s2[3],  po));
        pe = fmaf(a2.x, c2[4],  fmaf(-a2.y, s2[4],  pe));
        po = fmaf(a2.z, c2[5],  fmaf(-a2.w, s2[5],  po));
        pe = fmaf(a3.x, c2[6],  fmaf(-a3.y, s2[6],  pe));
        po = fmaf(a3.z, c2[7],  fmaf(-a3.w, s2[7],  po));
        pe = fmaf(a4.x, c2[8],  fmaf(-a4.y, s2[8],  pe));
        po = fmaf(a4.z, c2[9],  fmaf(-a4.w, s2[9],  po));
        pe = fmaf(a5.x, c2[10], fmaf(-a5.y, s2[10], pe));
        po = fmaf(a5.z, c2[11], fmaf(-a5.w, s2[11], po));
        float base = a0.x + pe;
        float v1 = fmaxf((base + po) * scale, 0.0f);   // t = tp
        float v2 = fmaxf((base - po) * scale, 0.0f);   // t = tp+32
        const float4* lp = (const float4*)&lwT[c][0];
        float4 l0 = lp[0], l1 = lp[1], l2 = lp[2], l3 = lp[3];
        acc1[0]  = fmaf(l0.x, v1, acc1[0]);  acc2[0]  = fmaf(l0.x, v2, acc2[0]);
        acc1[1]  = fmaf(l0.y, v1, acc1[1]);  acc2[1]  = fmaf(l0.y, v2, acc2[1]);
        acc1[2]  = fmaf(l0.z, v1, acc1[2]);  acc2[2]  = fmaf(l0.z, v2, acc2[2]);
        acc1[3]  = fmaf(l0.w, v1, acc1[3]);  acc2[3]  = fmaf(l0.w, v2, acc2[3]);
        acc1[4]  = fmaf(l1.x, v1, acc1[4]);  acc2[4]  = fmaf(l1.x, v2, acc2[4]);
        acc1[5]  = fmaf(l1.y, v1, acc1[5]);  acc2[5]  = fmaf(l1.y, v2, acc2[5]);
        acc1[6]  = fmaf(l1.z, v1, acc1[6]);  acc2[6]  = fmaf(l1.z, v2, acc2[6]);
        acc1[7]  = fmaf(l1.w, v1, acc1[7]);  acc2[7]  = fmaf(l1.w, v2, acc2[7]);
        acc1[8]  = fmaf(l2.x, v1, acc1[8]);  acc2[8]  = fmaf(l2.x, v2, acc2[8]);
        acc1[9]  = fmaf(l2.y, v1, acc1[9]);  acc2[9]  = fmaf(l2.y, v2, acc2[9]);
        acc1[10] = fmaf(l2.z, v1, acc1[10]); acc2[10] = fmaf(l2.z, v2, acc2[10]);
        acc1[11] = fmaf(l2.w, v1, acc1[11]); acc2[11] = fmaf(l2.w, v2, acc2[11]);
        acc1[12] = fmaf(l3.x, v1, acc1[12]); acc2[12] = fmaf(l3.x, v2, acc2[12]);
        acc1[13] = fmaf(l3.y, v1, acc1[13]); acc2[13] = fmaf(l3.y, v2, acc2[13]);
        acc1[14] = fmaf(l3.z, v1, acc1[14]); acc2[14] = fmaf(l3.z, v2, acc2[14]);
        acc1[15] = fmaf(l3.w, v1, acc1[15]); acc2[15] = fmaf(l3.w, v2, acc2[15]);
    }

    long obase = (long)b * 16 * 262144 + (long)(xy0 + slot) * 64;
    #pragma unroll
    for (int o = 0; o < 16; o++) {
        out[obase + (long)o * 262144 + tp]      = acc1[o];
        out[obase + (long)o * 262144 + tp + 32] = acc2[o];
    }
}

// ---------------------------------------------------------------------------
extern "C" void kernel_launch(void* const* d_in, const int* in_sizes, int n_in,
                              void* d_out, int out_size) {
    const float* x    = (const float*)d_in[0];
    const float* w1   = (const float*)d_in[1];
    const float* w2   = (const float*)d_in[2];
    const float* w3   = (const float*)d_in[3];
    const float* w4   = (const float*)d_in[4];
    const float* lo_w = (const float*)d_in[5];
    const float* lo_b = (const float*)d_in[6];
    float* out = (float*)d_out;

    k1w<<<4672, 128>>>(x, w1, w2, w3, w4);   // k1 (4096 blocks) + kw (576 blocks)
    k2_fft_y<<<1024, 96>>>();
    k3_fft_x<<<256, 144>>>();
    k4_mix<<<NFREQ/4, 512>>>();
    k5_ifft_x<<<768, 256>>>();
    k6_ifft_y<<<2048, 256>>>();
    k7_final<<<4096, 256>>>(lo_w, lo_b, out);
}